// round 5
// baseline (speedup 1.0000x reference)
#include <cuda_runtime.h>
#include <cstdint>

#define NNODES_MAX 100000
#define EDGES_MAX  1600000
#define DH 128
#define NGRAPH 512

// ---------------- scratch (static device globals; no allocation) ------------
__device__ float g_h[NNODES_MAX * DH];       // layer output h
__device__ float g_agg[NNODES_MAX * DH];     // h + A*h (gather output)
__device__ float g_pool[NGRAPH * DH];        // per-graph feature sums
__device__ float g_cnt[NGRAPH];              // per-graph node counts
__device__ int   g_deg[NNODES_MAX];          // in-degree histogram
__device__ int   g_cur[NNODES_MAX];          // fill cursors (seeded by scan)
__device__ int   g_rowptr[NNODES_MAX + 1];   // CSR row pointers (by dst)
__device__ int   g_col[EDGES_MAX];           // CSR column indices (src nodes)

// ---------------- helpers ---------------------------------------------------
__device__ __forceinline__ void red4(float* p, float4 v) {
    asm volatile("red.global.add.v4.f32 [%0], {%1,%2,%3,%4};"
                 :: "l"(p), "f"(v.x), "f"(v.y), "f"(v.z), "f"(v.w)
                 : "memory");
}

// ---------------- init: zero pool/cnt/deg ------------------------------------
__global__ void init_kernel(int n) {
    int i = blockIdx.x * blockDim.x + threadIdx.x;
    if (i < NGRAPH * DH) g_pool[i] = 0.f;
    if (i < NGRAPH) g_cnt[i] = 0.f;
    if (i < n) g_deg[i] = 0;
}

// fused: degree histogram (over E) + per-graph node counts (over N)
__global__ void hist_count_kernel(const int* __restrict__ ei,
                                  const int* __restrict__ batch, int E, int N) {
    int i = blockIdx.x * blockDim.x + threadIdx.x;
    if (i < E) atomicAdd(&g_deg[ei[E + i]], 1);   // dst
    if (i < N) atomicAdd(&g_cnt[batch[i]], 1.0f);
}

// single-block exclusive scan of g_deg into g_rowptr; also seeds g_cur
__global__ void scan_kernel(int n) {
    const int T = 1024;
    __shared__ int part[T];
    int t = threadIdx.x;
    int C = (n + T - 1) / T;
    int beg = t * C;
    int end = beg + C < n ? beg + C : n;
    int s = 0;
    for (int i = beg; i < end; i++) s += g_deg[i];
    part[t] = s;
    __syncthreads();
    for (int off = 1; off < T; off <<= 1) {
        int v = (t >= off) ? part[t - off] : 0;
        __syncthreads();
        part[t] += v;
        __syncthreads();
    }
    int run = (t == 0) ? 0 : part[t - 1];
    for (int i = beg; i < end; i++) {
        g_rowptr[i] = run;
        g_cur[i]    = run;
        run += g_deg[i];
    }
    if (t == 0) g_rowptr[n] = part[T - 1];
}

__global__ void fill_kernel(const int* __restrict__ ei, int E) {
    int i = blockIdx.x * blockDim.x + threadIdx.x;
    if (i >= E) return;
    int s = ei[i];
    int d = ei[E + i];
    int pos = atomicAdd(&g_cur[d], 1);
    g_col[pos] = s;
}

// ---------------- gather: g_agg[n] = src[n] + sum_{j in N(n)} src[j] ---------
// one warp per node; lane handles one float4; 8-deep MLP, 4 accumulators
template<bool FIRST>
__global__ void gather_kernel(const float* __restrict__ x, int N) {
    int w    = (blockIdx.x * blockDim.x + threadIdx.x) >> 5;
    int lane = threadIdx.x & 31;
    if (w >= N) return;
    const float4* __restrict__ src = FIRST ? reinterpret_cast<const float4*>(x)
                                           : reinterpret_cast<const float4*>(g_h);
    const int beg = g_rowptr[w];
    const int end = g_rowptr[w + 1];

    float4 a0 = src[w * 32 + lane];                // seed: own features
    float4 a1 = make_float4(0.f, 0.f, 0.f, 0.f);
    float4 a2 = make_float4(0.f, 0.f, 0.f, 0.f);
    float4 a3 = make_float4(0.f, 0.f, 0.f, 0.f);

    int j = beg;
    for (; j + 8 <= end; j += 8) {
        // uniform broadcast loads of 8 indices (same addr across warp)
        int s0 = g_col[j + 0], s1 = g_col[j + 1], s2 = g_col[j + 2], s3 = g_col[j + 3];
        int s4 = g_col[j + 4], s5 = g_col[j + 5], s6 = g_col[j + 6], s7 = g_col[j + 7];
        // 8 independent gathers in flight
        float4 v0 = src[s0 * 32 + lane];
        float4 v1 = src[s1 * 32 + lane];
        float4 v2 = src[s2 * 32 + lane];
        float4 v3 = src[s3 * 32 + lane];
        float4 v4 = src[s4 * 32 + lane];
        float4 v5 = src[s5 * 32 + lane];
        float4 v6 = src[s6 * 32 + lane];
        float4 v7 = src[s7 * 32 + lane];
        a0.x += v0.x; a0.y += v0.y; a0.z += v0.z; a0.w += v0.w;
        a1.x += v1.x; a1.y += v1.y; a1.z += v1.z; a1.w += v1.w;
        a2.x += v2.x; a2.y += v2.y; a2.z += v2.z; a2.w += v2.w;
        a3.x += v3.x; a3.y += v3.y; a3.z += v3.z; a3.w += v3.w;
        a0.x += v4.x; a0.y += v4.y; a0.z += v4.z; a0.w += v4.w;
        a1.x += v5.x; a1.y += v5.y; a1.z += v5.z; a1.w += v5.w;
        a2.x += v6.x; a2.y += v6.y; a2.z += v6.z; a2.w += v6.w;
        a3.x += v7.x; a3.y += v7.y; a3.z += v7.z; a3.w += v7.w;
    }
    for (; j < end; j++) {
        float4 v = src[g_col[j] * 32 + lane];
        a0.x += v.x; a0.y += v.y; a0.z += v.z; a0.w += v.w;
    }
    a0.x += a1.x + a2.x + a3.x;
    a0.y += a1.y + a2.y + a3.y;
    a0.z += a1.z + a2.z + a3.z;
    a0.w += a1.w + a2.w + a3.w;
    reinterpret_cast<float4*>(g_agg)[w * 32 + lane] = a0;
}

// ---------------- fused GEMM: out = act( g_agg @ W^T + b ) -------------------
// C[i][j] = sum_k A[i][k] * W[j][k];  BM=128, BN=128, BK=32, 256 threads, 8x8
#define GBM 128
#define GBK 32

template<bool RELU, bool POOL>
__global__ __launch_bounds__(256)
void gemm_kernel(const float* __restrict__ W, const float* __restrict__ bias,
                 const int* __restrict__ batch, int M) {
    __shared__ float As[GBK][GBM + 4];   // transposed: As[k][m]
    __shared__ float Ws[GBK][GBM + 4];   // transposed: Ws[k][j]

    const int tid = threadIdx.x;
    const int tx  = tid & 15;            // 16 col-groups * 8 cols
    const int ty  = tid >> 4;            // 16 row-groups * 8 rows
    const int rowBase = blockIdx.x * GBM;

    float acc[8][8];
#pragma unroll
    for (int r = 0; r < 8; r++)
#pragma unroll
        for (int c = 0; c < 8; c++) acc[r][c] = 0.f;

    const int lr = tid >> 3;             // 0..31
    const int lk = (tid & 7) * 4;        // 0,4,...,28

#pragma unroll
    for (int kc = 0; kc < DH; kc += GBK) {
        // stage A tile (128 rows x 32 cols), transposed into As[k][m]
#pragma unroll
        for (int p = 0; p < 4; p++) {
            int r = lr + p * 32;
            int grow = rowBase + r;
            if (grow >= M) grow = M - 1;
            float4 v = *reinterpret_cast<const float4*>(&g_agg[grow * DH + kc + lk]);
            As[lk + 0][r] = v.x; As[lk + 1][r] = v.y;
            As[lk + 2][r] = v.z; As[lk + 3][r] = v.w;
        }
        // stage W tile: Ws[k][j] = W[j][kc+k]
#pragma unroll
        for (int p = 0; p < 4; p++) {
            int j = lr + p * 32;
            float4 v = *reinterpret_cast<const float4*>(&W[j * DH + kc + lk]);
            Ws[lk + 0][j] = v.x; Ws[lk + 1][j] = v.y;
            Ws[lk + 2][j] = v.z; Ws[lk + 3][j] = v.w;
        }
        __syncthreads();
#pragma unroll
        for (int k = 0; k < GBK; k++) {
            float4 a0 = *reinterpret_cast<const float4*>(&As[k][ty * 8]);
            float4 a1 = *reinterpret_cast<const float4*>(&As[k][ty * 8 + 4]);
            float4 w0 = *reinterpret_cast<const float4*>(&Ws[k][tx * 8]);
            float4 w1 = *reinterpret_cast<const float4*>(&Ws[k][tx * 8 + 4]);
            float av[8] = {a0.x, a0.y, a0.z, a0.w, a1.x, a1.y, a1.z, a1.w};
            float wv[8] = {w0.x, w0.y, w0.z, w0.w, w1.x, w1.y, w1.z, w1.w};
#pragma unroll
            for (int r = 0; r < 8; r++)
#pragma unroll
                for (int c = 0; c < 8; c++)
                    acc[r][c] = fmaf(av[r], wv[c], acc[r][c]);
        }
        __syncthreads();
    }

    float4 bia0 = *reinterpret_cast<const float4*>(&bias[tx * 8]);
    float4 bia1 = *reinterpret_cast<const float4*>(&bias[tx * 8 + 4]);
#pragma unroll
    for (int r = 0; r < 8; r++) {
        int row = rowBase + ty * 8 + r;
        if (row >= M) continue;
        float4 o0, o1;
        o0.x = acc[r][0] + bia0.x; o0.y = acc[r][1] + bia0.y;
        o0.z = acc[r][2] + bia0.z; o0.w = acc[r][3] + bia0.w;
        o1.x = acc[r][4] + bia1.x; o1.y = acc[r][5] + bia1.y;
        o1.z = acc[r][6] + bia1.z; o1.w = acc[r][7] + bia1.w;
        if (RELU) {
            o0.x = fmaxf(o0.x, 0.f); o0.y = fmaxf(o0.y, 0.f);
            o0.z = fmaxf(o0.z, 0.f); o0.w = fmaxf(o0.w, 0.f);
            o1.x = fmaxf(o1.x, 0.f); o1.y = fmaxf(o1.y, 0.f);
            o1.z = fmaxf(o1.z, 0.f); o1.w = fmaxf(o1.w, 0.f);
        }
        *reinterpret_cast<float4*>(&g_h[row * DH + tx * 8])     = o0;
        *reinterpret_cast<float4*>(&g_h[row * DH + tx * 8 + 4]) = o1;
        if (POOL) {
            int b = batch[row];
            red4(&g_pool[b * DH + tx * 8],     o0);
            red4(&g_pool[b * DH + tx * 8 + 4], o1);
        }
    }
}

// ---------------- head: out[g][o] = dot(pool[g]/cnt[g], Wg[o]) + bg[o] ------
__global__ void final_kernel(const float* __restrict__ Wg,
                             const float* __restrict__ bg,
                             float* __restrict__ out) {
    int g = blockIdx.x;
    int lane = threadIdx.x;
    float4 p = reinterpret_cast<const float4*>(g_pool)[g * 32 + lane];
    float c = fmaxf(g_cnt[g], 1.0f);
#pragma unroll
    for (int o = 0; o < 10; o++) {
        float4 w = reinterpret_cast<const float4*>(Wg)[o * 32 + lane];
        float s = p.x * w.x + p.y * w.y + p.z * w.z + p.w * w.w;
#pragma unroll
        for (int off = 16; off; off >>= 1) s += __shfl_xor_sync(0xffffffffu, s, off);
        if (lane == 0) out[g * 10 + o] = s / c + bg[o];
    }
}

// ---------------- launch ----------------------------------------------------
extern "C" void kernel_launch(void* const* d_in, const int* in_sizes, int n_in,
                              void* d_out, int out_size) {
    const float* x     = (const float*)d_in[0];
    const int*   ei    = (const int*)d_in[1];      // int32 (JAX x64 disabled)
    const int*   batch = (const int*)d_in[2];
    const float* W0 = (const float*)d_in[3];
    const float* b0 = (const float*)d_in[4];
    const float* W1 = (const float*)d_in[5];
    const float* b1 = (const float*)d_in[6];
    const float* W2 = (const float*)d_in[7];
    const float* b2 = (const float*)d_in[8];
    const float* Wg = (const float*)d_in[9];
    const float* bg = (const float*)d_in[10];
    float* out = (float*)d_out;

    const int N = in_sizes[0] / DH;     // 100000
    const int E = in_sizes[1] / 2;      // 1600000

    const int gemm_grid = (N + GBM - 1) / GBM;
    const int gat_grid  = (N + 7) / 8;  // 8 warps/block, 1 node/warp

    // CSR build + init (amortized over 3 aggregations)
    init_kernel<<<(NGRAPH * DH > N ? NGRAPH * DH : N) / 512 + 1, 512>>>(N);
    hist_count_kernel<<<(E + 511) / 512, 512>>>(ei, batch, E, N);
    scan_kernel<<<1, 1024>>>(N);
    fill_kernel<<<(E + 511) / 512, 512>>>(ei, E);

    // layer 0
    gather_kernel<true><<<gat_grid, 256>>>(x, N);
    gemm_kernel<true, false><<<gemm_grid, 256>>>(W0, b0, nullptr, N);
    // layer 1
    gather_kernel<false><<<gat_grid, 256>>>(nullptr, N);
    gemm_kernel<true, false><<<gemm_grid, 256>>>(W1, b1, nullptr, N);
    // layer 2 + fused pooling
    gather_kernel<false><<<gat_grid, 256>>>(nullptr, N);
    gemm_kernel<false, true><<<gemm_grid, 256>>>(W2, b2, batch, N);

    final_kernel<<<NGRAPH, 32>>>(Wg, bg, out);
}

// round 7
// speedup vs baseline: 2.0743x; 2.0743x over previous
#include <cuda_runtime.h>
#include <cuda_fp16.h>
#include <cstdint>

#define NNODES_MAX 100000
#define EDGES_MAX  1600000
#define DH 128
#define NGRAPH 512

// ---------------- scratch (static device globals; no allocation) ------------
__device__ __half g_x16[NNODES_MAX * DH];    // input features, fp16
__device__ __half g_h16[NNODES_MAX * DH];    // layer output h, fp16
__device__ __half g_agg16[NNODES_MAX * DH];  // h + A*h, fp16
__device__ __half g_w16[3 * DH * DH];        // W0,W1,W2 in fp16
__device__ float  g_pool[NGRAPH * DH];       // per-graph sums (fp32)
__device__ float  g_cnt[NGRAPH];             // per-graph node counts
__device__ int    g_deg[NNODES_MAX];
__device__ int    g_cur[NNODES_MAX];
__device__ int    g_rowptr[NNODES_MAX + 1];
__device__ int    g_col[EDGES_MAX];

// ---------------- helpers ---------------------------------------------------
__device__ __forceinline__ void red2(float* p, float a, float b) {
    asm volatile("red.global.add.v2.f32 [%0], {%1,%2};"
                 :: "l"(p), "f"(a), "f"(b) : "memory");
}
__device__ __forceinline__ float4 h8_to_f4(uint2 u) {
    __half2 a = *reinterpret_cast<__half2*>(&u.x);
    __half2 b = *reinterpret_cast<__half2*>(&u.y);
    float2 fa = __half22float2(a), fb = __half22float2(b);
    return make_float4(fa.x, fa.y, fb.x, fb.y);
}

// ---------------- init: zero pool/cnt/deg ------------------------------------
__global__ void init_kernel(int n) {
    int i = blockIdx.x * blockDim.x + threadIdx.x;
    if (i < NGRAPH * DH) g_pool[i] = 0.f;
    if (i < NGRAPH) g_cnt[i] = 0.f;
    if (i < n) g_deg[i] = 0;
}

// fused: degree histogram (over E) + per-graph node counts (over N)
__global__ void hist_count_kernel(const int* __restrict__ ei,
                                  const int* __restrict__ batch, int E, int N) {
    int i = blockIdx.x * blockDim.x + threadIdx.x;
    if (i < E) atomicAdd(&g_deg[ei[E + i]], 1);   // dst
    if (i < N) atomicAdd(&g_cnt[batch[i]], 1.0f);
}

// single-block exclusive scan of g_deg into g_rowptr; also seeds g_cur
__global__ void scan_kernel(int n) {
    const int T = 1024;
    __shared__ int part[T];
    int t = threadIdx.x;
    int C = (n + T - 1) / T;
    int beg = t * C;
    int end = beg + C < n ? beg + C : n;
    int s = 0;
    for (int i = beg; i < end; i++) s += g_deg[i];
    part[t] = s;
    __syncthreads();
    for (int off = 1; off < T; off <<= 1) {
        int v = (t >= off) ? part[t - off] : 0;
        __syncthreads();
        part[t] += v;
        __syncthreads();
    }
    int run = (t == 0) ? 0 : part[t - 1];
    for (int i = beg; i < end; i++) {
        g_rowptr[i] = run;
        g_cur[i]    = run;
        run += g_deg[i];
    }
    if (t == 0) g_rowptr[n] = part[T - 1];
}

__global__ void fill_kernel(const int* __restrict__ ei, int E) {
    int i = blockIdx.x * blockDim.x + threadIdx.x;
    if (i >= E) return;
    int s = ei[i];
    int d = ei[E + i];
    int pos = atomicAdd(&g_cur[d], 1);
    g_col[pos] = s;
}

// ---------------- converters -------------------------------------------------
__global__ void convert_x_kernel(const float4* __restrict__ x, int n4) {
    int i = blockIdx.x * blockDim.x + threadIdx.x;
    if (i >= n4) return;
    float4 v = x[i];
    __half2* dst = reinterpret_cast<__half2*>(g_x16);
    dst[i * 2]     = __floats2half2_rn(v.x, v.y);
    dst[i * 2 + 1] = __floats2half2_rn(v.z, v.w);
}

__global__ void convert_w_kernel(const float4* __restrict__ w, int layer) {
    int i = blockIdx.x * blockDim.x + threadIdx.x;
    const int n4 = DH * DH / 4;   // 4096
    if (i >= n4) return;
    float4 v = w[i];
    __half2* dst = reinterpret_cast<__half2*>(&g_w16[layer * DH * DH]);
    dst[i * 2]     = __floats2half2_rn(v.x, v.y);
    dst[i * 2 + 1] = __floats2half2_rn(v.z, v.w);
}

// ---------------- gather: agg16[n] = src[n] + sum_{j in N(n)} src[j] ---------
// one warp per node; lane handles 4 halfs (uint2, 8B); R3-style shfl loop
__global__ void gather16_kernel(const __half* __restrict__ srcp, int N) {
    int w    = (blockIdx.x * blockDim.x + threadIdx.x) >> 5;
    int lane = threadIdx.x & 31;
    if (w >= N) return;
    const uint2* __restrict__ src = reinterpret_cast<const uint2*>(srcp);
    const int beg = g_rowptr[w];
    const int end = g_rowptr[w + 1];

    float4 acc = h8_to_f4(src[w * 32 + lane]);     // seed: own features
    for (int base = beg; base < end; base += 32) {
        int idx = (base + lane < end) ? g_col[base + lane] : 0;
        int cnt = end - base; if (cnt > 32) cnt = 32;
#pragma unroll 4
        for (int j = 0; j < cnt; j++) {
            int s = __shfl_sync(0xffffffffu, idx, j);
            float4 v = h8_to_f4(src[s * 32 + lane]);
            acc.x += v.x; acc.y += v.y; acc.z += v.z; acc.w += v.w;
        }
    }
    uint2 o;
    *reinterpret_cast<__half2*>(&o.x) = __floats2half2_rn(acc.x, acc.y);
    *reinterpret_cast<__half2*>(&o.y) = __floats2half2_rn(acc.z, acc.w);
    reinterpret_cast<uint2*>(g_agg16)[w * 32 + lane] = o;
}

// ---------------- tensor-core GEMM: C = act( agg16 @ W^T + b ) ---------------
// mma.sync m16n8k16 f16*f16+f32. BM=128, BN=128, BK=64 (2 stages), 8 warps.
// warp (wid%2, wid/2) owns m64 x n32 = 4x4 mma tiles.
template<bool RELU, bool POOL>
__global__ __launch_bounds__(256)
void hgemm_kernel(const __half* __restrict__ Wh, const float* __restrict__ bias,
                  const int* __restrict__ batch, int M) {
    __shared__ __half As[128 * 72];   // [m][k], stride 72 (pad 8) -> conflict-free h2 frags
    __shared__ __half Ws[128 * 72];   // [n][k]

    const int tid  = threadIdx.x;
    const int wid  = tid >> 5;
    const int lane = tid & 31;
    const int g    = lane >> 2;       // 0..7
    const int c    = (lane & 3) * 2;  // 0,2,4,6
    const int mrow = (wid & 1) * 64;
    const int ncol = (wid >> 1) * 32;
    const int rowBase = blockIdx.x * 128;

    float acc[4][4][4];
#pragma unroll
    for (int mt = 0; mt < 4; mt++)
#pragma unroll
        for (int nt = 0; nt < 4; nt++)
#pragma unroll
            for (int q = 0; q < 4; q++) acc[mt][nt][q] = 0.f;

#pragma unroll
    for (int kc = 0; kc < DH; kc += 64) {
        __syncthreads();
        // stage A[128][64] and W[128][64] (8 halfs = uint4 per thread-chunk)
#pragma unroll
        for (int t = 0; t < 4; t++) {
            int idx = tid + t * 256;
            int row = idx >> 3;
            int ch  = (idx & 7) * 8;
            int grow = rowBase + row;
            if (grow >= M) grow = M - 1;
            *reinterpret_cast<uint4*>(&As[row * 72 + ch]) =
                *reinterpret_cast<const uint4*>(&g_agg16[grow * DH + kc + ch]);
            *reinterpret_cast<uint4*>(&Ws[row * 72 + ch]) =
                *reinterpret_cast<const uint4*>(&Wh[row * DH + kc + ch]);
        }
        __syncthreads();

#pragma unroll
        for (int kk = 0; kk < 4; kk++) {
            const int k0 = kk * 16;
            uint32_t af[4][4], bf[4][2];
#pragma unroll
            for (int mt = 0; mt < 4; mt++) {
                int rb = (mrow + mt * 16 + g) * 72 + k0 + c;
                af[mt][0] = *reinterpret_cast<const uint32_t*>(&As[rb]);
                af[mt][1] = *reinterpret_cast<const uint32_t*>(&As[rb + 8 * 72]);
                af[mt][2] = *reinterpret_cast<const uint32_t*>(&As[rb + 8]);
                af[mt][3] = *reinterpret_cast<const uint32_t*>(&As[rb + 8 * 72 + 8]);
            }
#pragma unroll
            for (int nt = 0; nt < 4; nt++) {
                int cb = (ncol + nt * 8 + g) * 72 + k0 + c;
                bf[nt][0] = *reinterpret_cast<const uint32_t*>(&Ws[cb]);
                bf[nt][1] = *reinterpret_cast<const uint32_t*>(&Ws[cb + 8]);
            }
#pragma unroll
            for (int mt = 0; mt < 4; mt++)
#pragma unroll
                for (int nt = 0; nt < 4; nt++) {
                    asm volatile(
                        "mma.sync.aligned.m16n8k16.row.col.f32.f16.f16.f32 "
                        "{%0,%1,%2,%3}, {%4,%5,%6,%7}, {%8,%9}, {%0,%1,%2,%3};"
                        : "+f"(acc[mt][nt][0]), "+f"(acc[mt][nt][1]),
                          "+f"(acc[mt][nt][2]), "+f"(acc[mt][nt][3])
                        : "r"(af[mt][0]), "r"(af[mt][1]), "r"(af[mt][2]), "r"(af[mt][3]),
                          "r"(bf[nt][0]), "r"(bf[nt][1]));
                }
        }
    }

    // epilogue
#pragma unroll
    for (int nt = 0; nt < 4; nt++) {
        int col = ncol + nt * 8 + c;
        float2 bb = *reinterpret_cast<const float2*>(&bias[col]);
#pragma unroll
        for (int mt = 0; mt < 4; mt++) {
            int row0 = rowBase + mrow + mt * 16 + g;
            int row1 = row0 + 8;
            float c0 = acc[mt][nt][0] + bb.x;
            float c1 = acc[mt][nt][1] + bb.y;
            float c2 = acc[mt][nt][2] + bb.x;
            float c3 = acc[mt][nt][3] + bb.y;
            if (RELU) {
                c0 = fmaxf(c0, 0.f); c1 = fmaxf(c1, 0.f);
                c2 = fmaxf(c2, 0.f); c3 = fmaxf(c3, 0.f);
            }
            if (POOL) {
                if (row0 < M) red2(&g_pool[batch[row0] * DH + col], c0, c1);
                if (row1 < M) red2(&g_pool[batch[row1] * DH + col], c2, c3);
            } else {
                if (row0 < M)
                    *reinterpret_cast<__half2*>(&g_h16[row0 * DH + col]) =
                        __floats2half2_rn(c0, c1);
                if (row1 < M)
                    *reinterpret_cast<__half2*>(&g_h16[row1 * DH + col]) =
                        __floats2half2_rn(c2, c3);
            }
        }
    }
}

// ---------------- head: out[g][o] = dot(pool[g]/cnt[g], Wg[o]) + bg[o] ------
__global__ void final_kernel(const float* __restrict__ Wg,
                             const float* __restrict__ bg,
                             float* __restrict__ out) {
    int g = blockIdx.x;
    int lane = threadIdx.x;
    float4 p = reinterpret_cast<const float4*>(g_pool)[g * 32 + lane];
    float c = fmaxf(g_cnt[g], 1.0f);
#pragma unroll
    for (int o = 0; o < 10; o++) {
        float4 w = reinterpret_cast<const float4*>(Wg)[o * 32 + lane];
        float s = p.x * w.x + p.y * w.y + p.z * w.z + p.w * w.w;
#pragma unroll
        for (int off = 16; off; off >>= 1) s += __shfl_xor_sync(0xffffffffu, s, off);
        if (lane == 0) out[g * 10 + o] = s / c + bg[o];
    }
}

// ---------------- launch ----------------------------------------------------
extern "C" void kernel_launch(void* const* d_in, const int* in_sizes, int n_in,
                              void* d_out, int out_size) {
    const float* x     = (const float*)d_in[0];
    const int*   ei    = (const int*)d_in[1];      // int32 (JAX x64 disabled)
    const int*   batch = (const int*)d_in[2];
    const float* W0 = (const float*)d_in[3];
    const float* b0 = (const float*)d_in[4];
    const float* W1 = (const float*)d_in[5];
    const float* b1 = (const float*)d_in[6];
    const float* W2 = (const float*)d_in[7];
    const float* b2 = (const float*)d_in[8];
    const float* Wg = (const float*)d_in[9];
    const float* bg = (const float*)d_in[10];
    float* out = (float*)d_out;

    const int N = in_sizes[0] / DH;     // 100000
    const int E = in_sizes[1] / 2;      // 1600000

    const int gemm_grid = (N + 127) / 128;
    const int gat_grid  = (N + 7) / 8;  // 8 warps/block, 1 node/warp
    const int n4 = N * (DH / 4);

    __half* w16;
    cudaGetSymbolAddress((void**)&w16, g_w16);

    // CSR build + init + fp16 conversions
    init_kernel<<<(NGRAPH * DH > N ? NGRAPH * DH : N) / 512 + 1, 512>>>(N);
    hist_count_kernel<<<(E + 511) / 512, 512>>>(ei, batch, E, N);
    scan_kernel<<<1, 1024>>>(N);
    fill_kernel<<<(E + 511) / 512, 512>>>(ei, E);
    convert_x_kernel<<<(n4 + 511) / 512, 512>>>(reinterpret_cast<const float4*>(x), n4);
    convert_w_kernel<<<8, 512>>>(reinterpret_cast<const float4*>(W0), 0);
    convert_w_kernel<<<8, 512>>>(reinterpret_cast<const float4*>(W1), 1);
    convert_w_kernel<<<8, 512>>>(reinterpret_cast<const float4*>(W2), 2);

    __half* x16;  cudaGetSymbolAddress((void**)&x16, g_x16);
    __half* h16;  cudaGetSymbolAddress((void**)&h16, g_h16);

    // layer 0
    gather16_kernel<<<gat_grid, 256>>>(x16, N);
    hgemm_kernel<true, false><<<gemm_grid, 256>>>(w16, b0, nullptr, N);
    // layer 1
    gather16_kernel<<<gat_grid, 256>>>(h16, N);
    hgemm_kernel<true, false><<<gemm_grid, 256>>>(w16 + DH * DH, b1, nullptr, N);
    // layer 2 + fused pooling
    gather16_kernel<<<gat_grid, 256>>>(h16, N);
    hgemm_kernel<false, true><<<gemm_grid, 256>>>(w16 + 2 * DH * DH, b2, batch, N);

    final_kernel<<<NGRAPH, 32>>>(Wg, bg, out);
}